// round 3
// baseline (speedup 1.0000x reference)
#include <cuda_runtime.h>

// Problem shapes (fixed for this bench instance)
#define MAXB 16
#define MAXC 1024
#define MAXD 768

#define BM 32
#define BN 64
#define BK 32

__device__ float    g_Pn[MAXC * MAXD];                       // normalized prototypes
__device__ float    g_Fn[(size_t)MAXB * MAXC * MAXD];        // gathered+normalized positive anchor rows
__device__ float    g_S[(size_t)MAXB * MAXC * MAXC];         // raw sim rows for positive anchors
__device__ int      g_pos_idx[MAXB * MAXC];
__device__ int      g_npos[MAXB];
__device__ unsigned g_rand_bits[MAXB * (MAXC / 32)];
__device__ unsigned g_pos_bits[MAXB * (MAXC / 32)];
__device__ float    g_loss[MAXB * MAXC];

__device__ __forceinline__ float neg_inf() { return __int_as_float(0xff800000); }

__device__ __forceinline__ bool is_pos(int b, int e, int C) {
    return (g_pos_bits[((b * C + e) >> 5)] >> (e & 31)) & 1u;
}

__device__ __forceinline__ float block_reduce_sum(float v, float* sm) {
    int t = threadIdx.x, n = blockDim.x;
    sm[t] = v;
    __syncthreads();
    for (int off = n >> 1; off > 0; off >>= 1) {
        if (t < off) sm[t] += sm[t + off];
        __syncthreads();
    }
    float r = sm[0];
    __syncthreads();
    return r;
}

// ---------------------------------------------------------------------------
// K0: targets dtype detection (int32 vs int64 layout) + build positive bitmask.
// int64 0/1 values little-endian => all odd 32-bit words are 0.
// ---------------------------------------------------------------------------
__global__ void k_mask(const int* __restrict__ w, int nelem) {
    __shared__ int any;
    int tid = threadIdx.x;
    if (tid == 0) any = 0;
    __syncthreads();
    int local = 0;
    for (int i = 2 * tid + 1; i < nelem; i += 2 * blockDim.x) local |= w[i];
    if (local) atomicOr(&any, 1);
    __syncthreads();
    int stride = any ? 1 : 2;           // int32 layout -> 1, int64 layout -> 2
    int nwords = nelem / 32;
    for (int wi = tid; wi < nwords; wi += blockDim.x) {
        unsigned bits = 0;
        #pragma unroll 8
        for (int bb = 0; bb < 32; bb++) {
            int e = wi * 32 + bb;
            if (w[e * stride] != 0) bits |= (1u << bb);
        }
        g_pos_bits[wi] = bits;
    }
}

// ---------------------------------------------------------------------------
// K1: normalize prototypes
// ---------------------------------------------------------------------------
__global__ void k_norm_p(const float* __restrict__ p, int D) {
    int e = blockIdx.x;
    const float* row = p + (size_t)e * D;
    __shared__ float red[256];
    float ss = 0.f;
    for (int k = threadIdx.x; k < D; k += blockDim.x) { float v = row[k]; ss += v * v; }
    float tot = block_reduce_sum(ss, red);
    float inv = 1.f / fmaxf(sqrtf(tot), 1e-12f);
    float* dst = g_Pn + (size_t)e * D;
    for (int k = threadIdx.x; k < D; k += blockDim.x) dst[k] = row[k] * inv;
}

// ---------------------------------------------------------------------------
// K2: per-batch random-negative selection (top-Krand of scores over negatives
// == threshold membership). One block per batch, blockDim==C, bitonic sort.
// ---------------------------------------------------------------------------
__global__ void k_rand(const float* __restrict__ rs, int C, int Krand) {
    int b = blockIdx.x, e = threadIdx.x;
    __shared__ float key[MAXC];
    float sc = rs[b * C + e];
    bool neg = !is_pos(b, e, C);
    key[e] = neg ? sc : neg_inf();
    __syncthreads();
    for (int k = 2; k <= C; k <<= 1)
        for (int j = k >> 1; j > 0; j >>= 1) {
            int ixj = e ^ j;
            if (ixj > e) {
                float a = key[e], c2 = key[ixj];
                bool up = ((e & k) == 0);
                if ((a > c2) == up) { key[e] = c2; key[ixj] = a; }
            }
            __syncthreads();
        }
    float thresh = key[C - Krand];          // Krand-th largest value
    bool member = neg && (sc >= thresh);
    unsigned bal = __ballot_sync(0xffffffffu, member);
    if ((e & 31) == 0) g_rand_bits[b * (C / 32) + (e >> 5)] = bal;
}

// ---------------------------------------------------------------------------
// K3: per-batch compaction of positive anchor indices (inclusive scan).
// ---------------------------------------------------------------------------
__global__ void k_compact(int C) {
    int b = blockIdx.x, e = threadIdx.x;
    __shared__ int sc[MAXC];
    int flag = is_pos(b, e, C) ? 1 : 0;
    sc[e] = flag;
    __syncthreads();
    for (int off = 1; off < C; off <<= 1) {
        int v = (e >= off) ? sc[e - off] : 0;
        __syncthreads();
        sc[e] += v;
        __syncthreads();
    }
    if (flag) g_pos_idx[b * C + (sc[e] - 1)] = e;
    if (e == C - 1) g_npos[b] = sc[e];
}

// ---------------------------------------------------------------------------
// K4: gather + normalize positive anchor rows into g_Fn (dense by slot).
// ---------------------------------------------------------------------------
__global__ void k_gnorm(const float* __restrict__ f, int C, int D) {
    int b = blockIdx.y, x = blockIdx.x;
    if (x >= g_npos[b]) return;
    int c = g_pos_idx[b * C + x];
    const float* row = f + ((size_t)b * C + c) * D;
    __shared__ float red[256];
    float ss = 0.f;
    for (int k = threadIdx.x; k < D; k += blockDim.x) { float v = row[k]; ss += v * v; }
    float tot = block_reduce_sum(ss, red);
    float inv = 1.f / fmaxf(sqrtf(tot), 1e-12f);
    float* dst = g_Fn + ((size_t)b * C + x) * D;
    for (int k = threadIdx.x; k < D; k += blockDim.x) dst[k] = row[k] * inv;
}

// ---------------------------------------------------------------------------
// K5: skinny GEMM S = Fn @ Pn^T (raw similarities).
// ---------------------------------------------------------------------------
__global__ void k_gemm(int C, int D) {
    int b = blockIdx.z;
    int m0 = blockIdx.y * BM;
    if (m0 >= g_npos[b]) return;
    int n0 = blockIdx.x * BN;

    __shared__ float As[BK][BM + 1];
    __shared__ float Bs[BK][BN + 1];

    int tid = threadIdx.x;
    int tx = tid & 15, ty = tid >> 4;
    float acc[2][4] = {};

    const float* Abase = g_Fn + ((size_t)b * C + m0) * D;
    const float* Bbase = g_Pn + (size_t)n0 * D;

    for (int k0 = 0; k0 < D; k0 += BK) {
        {   // A tile: 32 rows x 32 k, float4, stored transposed [k][m]
            int idx = tid * 4;
            int m = idx >> 5, k = idx & 31;
            float4 v = *(const float4*)(Abase + (size_t)m * D + k0 + k);
            As[k + 0][m] = v.x; As[k + 1][m] = v.y; As[k + 2][m] = v.z; As[k + 3][m] = v.w;
        }
        #pragma unroll
        for (int r = 0; r < 2; r++) {   // B tile: 64 rows x 32 k
            int idx = (tid + r * 256) * 4;
            int e = idx >> 5, k = idx & 31;
            float4 v = *(const float4*)(Bbase + (size_t)e * D + k0 + k);
            Bs[k + 0][e] = v.x; Bs[k + 1][e] = v.y; Bs[k + 2][e] = v.z; Bs[k + 3][e] = v.w;
        }
        __syncthreads();
        #pragma unroll
        for (int kk = 0; kk < BK; kk++) {
            float a0 = As[kk][2 * ty], a1 = As[kk][2 * ty + 1];
            float b0 = Bs[kk][4 * tx + 0], b1 = Bs[kk][4 * tx + 1];
            float b2 = Bs[kk][4 * tx + 2], b3 = Bs[kk][4 * tx + 3];
            acc[0][0] += a0 * b0; acc[0][1] += a0 * b1; acc[0][2] += a0 * b2; acc[0][3] += a0 * b3;
            acc[1][0] += a1 * b0; acc[1][1] += a1 * b1; acc[1][2] += a1 * b2; acc[1][3] += a1 * b3;
        }
        __syncthreads();
    }
    #pragma unroll
    for (int r = 0; r < 2; r++) {
        int m = m0 + 2 * ty + r;
        float4 v = make_float4(acc[r][0], acc[r][1], acc[r][2], acc[r][3]);
        *(float4*)(g_S + ((size_t)b * C + m) * C + n0 + 4 * tx) = v;
    }
}

// ---------------------------------------------------------------------------
// K6: per-anchor hard-negative top-K (bitonic sort) + stable logsumexp over
// (hard top-Khard) ⊎ (rand-selected), then per-anchor loss.
// ---------------------------------------------------------------------------
__global__ void k_select(int C, int Khard, float tau_inv) {
    int b = blockIdx.y, x = blockIdx.x;
    if (x >= g_npos[b]) return;

    __shared__ float row[MAXC];
    __shared__ float key[MAXC];
    __shared__ float red[512];

    int tid = threadIdx.x;
    const float* srow = g_S + ((size_t)b * C + x) * C;
    for (int e = tid; e < C; e += blockDim.x) {
        float s = srow[e];
        row[e] = s;
        key[e] = is_pos(b, e, C) ? neg_inf() : s;
    }
    __syncthreads();

    // bitonic sort ascending over C elements, blockDim=512 threads x 2 elems
    for (int k = 2; k <= C; k <<= 1)
        for (int j = k >> 1; j > 0; j >>= 1) {
            for (int i = tid; i < C; i += blockDim.x) {
                int ixj = i ^ j;
                if (ixj > i) {
                    float a = key[i], c2 = key[ixj];
                    bool up = ((i & k) == 0);
                    if ((a > c2) == up) { key[i] = c2; key[ixj] = a; }
                }
            }
            __syncthreads();
        }

    float m = key[C - 1];   // max negative raw sim; hard set always contains the max
    float part = 0.f;
    for (int i = tid; i < Khard; i += blockDim.x)
        part += expf((key[C - 1 - i] - m) * tau_inv);
    for (int e = tid; e < C; e += blockDim.x)
        if ((g_rand_bits[b * (C / 32) + (e >> 5)] >> (e & 31)) & 1u)
            part += expf((row[e] - m) * tau_inv);

    float total = block_reduce_sum(part, red);
    if (tid == 0) {
        float lse = m * tau_inv + logf(total);
        float pos = row[g_pos_idx[b * C + x]] * tau_inv;
        float mx = fmaxf(pos, lse), mn = fminf(pos, lse);
        float lap = mx + log1pf(expf(mn - mx));   // logaddexp(pos, lse)
        g_loss[b * C + x] = lap - pos;            // = -log_prob
    }
}

// ---------------------------------------------------------------------------
// K7: deterministic final reduction: mean over batches of (sum/clip(npos,1)).
// ---------------------------------------------------------------------------
__global__ void k_final(float* __restrict__ out, int B, int C) {
    __shared__ float red[256];
    int tid = threadIdx.x;
    float result = 0.f;
    for (int b = 0; b < B; b++) {
        int np = g_npos[b];
        float part = 0.f;
        for (int x = tid; x < np; x += blockDim.x) part += g_loss[b * C + x];
        float s = block_reduce_sum(part, red);
        if (tid == 0) result += s / (float)(np < 1 ? 1 : np);
    }
    if (tid == 0) out[0] = result / (float)B;
}

// ---------------------------------------------------------------------------
extern "C" void kernel_launch(void* const* d_in, const int* in_sizes, int n_in,
                              void* d_out, int out_size) {
    const float* f  = (const float*)d_in[0];
    const float* p  = (const float*)d_in[1];
    const int*   tw = (const int*)d_in[2];   // targets words (int32 or int64 layout)
    const float* rs = (const float*)d_in[3];

    int nf = in_sizes[0], npx = in_sizes[1], nt = in_sizes[2];
    int B = nf / npx;          // 16
    int C = nt / B;            // 1024
    int D = npx / C;           // 768
    int K = C - 1;
    int Khard = (int)((double)K * 0.3);   // 306
    int Krand = K - Khard;                // 717
    float tau_inv = 1.0f / 0.1f;

    k_mask   <<<1, 1024>>>(tw, nt);
    k_norm_p <<<C, 256>>>(p, D);
    k_rand   <<<B, C>>>(rs, C, Krand);
    k_compact<<<B, C>>>(C);
    k_gnorm  <<<dim3(C, B), 256>>>(f, C, D);
    k_gemm   <<<dim3(C / BN, C / BM, B), 256>>>(C, D);
    k_select <<<dim3(C, B), 512>>>(C, Khard, tau_inv);
    k_final  <<<1, 256>>>((float*)d_out, B, C);
}

// round 5
// speedup vs baseline: 2.6922x; 2.6922x over previous
#include <cuda_runtime.h>

// Fixed shapes for this bench instance
#define MAXB 16
#define MAXC 1024
#define MAXD 768

// GEMM tiling
#define GBM 64
#define GBN 64
#define GBK 16

__device__ float    g_Pn[MAXC * MAXD];                 // normalized prototypes
__device__ float    g_Fn[(size_t)MAXB * MAXC * MAXD];  // packed normalized positive anchor rows
__device__ float    g_S[(size_t)MAXB * MAXC * MAXC];   // packed raw sim rows
__device__ int      g_row_b[MAXB * MAXC];              // packed row -> batch
__device__ int      g_row_c[MAXB * MAXC];              // packed row -> column (anchor label)
__device__ int      g_npos[MAXB];
__device__ int      g_batch_base[MAXB];
__device__ int      g_mtot;
__device__ unsigned g_rand_bits[MAXB * (MAXC / 32)];
__device__ unsigned g_pos_bits[MAXB * (MAXC / 32)];
__device__ float    g_loss[MAXB * MAXC];

__device__ __forceinline__ float neg_inf() { return __int_as_float(0xff800000); }

__device__ __forceinline__ bool is_pos(int b, int e, int C) {
    return (g_pos_bits[((b * C + e) >> 5)] >> (e & 31)) & 1u;
}

// float <-> order-preserving uint key
__device__ __forceinline__ unsigned f2key(float f) {
    unsigned u = __float_as_uint(f);
    return (u & 0x80000000u) ? ~u : (u | 0x80000000u);
}
__device__ __forceinline__ float key2f(unsigned k) {
    unsigned u = (k & 0x80000000u) ? (k ^ 0x80000000u) : ~k;
    return __uint_as_float(u);
}

// block reduce helpers (nwarps <= 8), smem buffers provided by caller
__device__ __forceinline__ float bred_sum_f(float v, float* sm, int nwarps) {
    int lane = threadIdx.x & 31, w = threadIdx.x >> 5;
    #pragma unroll
    for (int off = 16; off > 0; off >>= 1) v += __shfl_down_sync(0xffffffffu, v, off);
    if (lane == 0) sm[w] = v;
    __syncthreads();
    if (w == 0) {
        float x = (lane < nwarps) ? sm[lane] : 0.f;
        #pragma unroll
        for (int off = 4; off > 0; off >>= 1) x += __shfl_down_sync(0xffffffffu, x, off);
        if (lane == 0) sm[0] = x;
    }
    __syncthreads();
    float r = sm[0];
    __syncthreads();
    return r;
}
__device__ __forceinline__ int bred_sum_i(int v, int* sm, int nwarps) {
    int lane = threadIdx.x & 31, w = threadIdx.x >> 5;
    #pragma unroll
    for (int off = 16; off > 0; off >>= 1) v += __shfl_down_sync(0xffffffffu, v, off);
    if (lane == 0) sm[w] = v;
    __syncthreads();
    if (w == 0) {
        int x = (lane < nwarps) ? sm[lane] : 0;
        #pragma unroll
        for (int off = 4; off > 0; off >>= 1) x += __shfl_down_sync(0xffffffffu, x, off);
        if (lane == 0) sm[0] = x;
    }
    __syncthreads();
    int r = sm[0];
    __syncthreads();
    return r;
}
__device__ __forceinline__ unsigned bred_max_u(unsigned v, unsigned* sm, int nwarps) {
    int lane = threadIdx.x & 31, w = threadIdx.x >> 5;
    #pragma unroll
    for (int off = 16; off > 0; off >>= 1) v = max(v, __shfl_down_sync(0xffffffffu, v, off));
    if (lane == 0) sm[w] = v;
    __syncthreads();
    if (w == 0) {
        unsigned x = (lane < nwarps) ? sm[lane] : 0u;
        #pragma unroll
        for (int off = 4; off > 0; off >>= 1) x = max(x, __shfl_down_sync(0xffffffffu, x, off));
        if (lane == 0) sm[0] = x;
    }
    __syncthreads();
    unsigned r = sm[0];
    __syncthreads();
    return r;
}

// ---------------------------------------------------------------------------
// K0: targets dtype detection (int32 vs int64 layout) + positive bitmask.
// Detection scans ONLY the first nelem words (valid under BOTH layouts):
// int64 layout -> odd words are hi-words of 0/1 values (all zero);
// int32 layout -> odd words are real values (~5% nonzero).
// ---------------------------------------------------------------------------
__global__ void k_mask(const int* __restrict__ wds, int nelem) {
    __shared__ int any;
    int tid = threadIdx.x, lane = tid & 31, w = tid >> 5;
    if (tid == 0) any = 0;
    __syncthreads();
    int local = 0;
    for (int i = 2 * tid + 1; i < nelem; i += 2 * blockDim.x) local |= wds[i];
    if (local) atomicOr(&any, 1);
    __syncthreads();
    int stride = any ? 1 : 2;   // int32 layout -> 1, int64 layout -> 2
    int nwords = nelem / 32;
    for (int g = w; g < nwords; g += (int)(blockDim.x >> 5)) {
        int e = g * 32 + lane;
        int val = wds[(size_t)e * stride];
        unsigned bal = __ballot_sync(0xffffffffu, val != 0);
        if (lane == 0) g_pos_bits[g] = bal;
    }
}

// ---------------------------------------------------------------------------
// K1: normalize prototypes (192 threads, one float4 per thread)
// ---------------------------------------------------------------------------
__global__ void k_norm_p(const float* __restrict__ p, int D) {
    int e = blockIdx.x, tid = threadIdx.x;
    __shared__ float sm[8];
    const float4* row = (const float4*)(p + (size_t)e * D);
    float4 v = row[tid];
    float ss = v.x * v.x + v.y * v.y + v.z * v.z + v.w * v.w;
    float tot = bred_sum_f(ss, sm, 6);
    float inv = 1.f / fmaxf(sqrtf(tot), 1e-12f);
    float4 o = make_float4(v.x * inv, v.y * inv, v.z * inv, v.w * inv);
    ((float4*)(g_Pn + (size_t)e * D))[tid] = o;
}

// ---------------------------------------------------------------------------
// K2: per-batch random-negative selection (bitonic, proven correct).
// ---------------------------------------------------------------------------
__global__ void k_rand(const float* __restrict__ rs, int C, int Krand) {
    int b = blockIdx.x, e = threadIdx.x;
    __shared__ float key[MAXC];
    float sc = rs[b * C + e];
    bool neg = !is_pos(b, e, C);
    key[e] = neg ? sc : neg_inf();
    __syncthreads();
    for (int k = 2; k <= C; k <<= 1)
        for (int j = k >> 1; j > 0; j >>= 1) {
            int ixj = e ^ j;
            if (ixj > e) {
                float a = key[e], c2 = key[ixj];
                bool up = ((e & k) == 0);
                if ((a > c2) == up) { key[e] = c2; key[ixj] = a; }
            }
            __syncthreads();
        }
    float thresh = key[C - Krand];
    bool member = neg && (sc >= thresh);
    unsigned bal = __ballot_sync(0xffffffffu, member);
    if ((e & 31) == 0) g_rand_bits[b * (C / 32) + (e >> 5)] = bal;
}

// ---------------------------------------------------------------------------
// K3: compact positive anchors into one packed list (warp scans). <<<1, B*32>>>
// ---------------------------------------------------------------------------
__global__ void k_compact(int B) {
    __shared__ int sm_npos[MAXB], sm_base[MAXB];
    int tid = threadIdx.x, lane = tid & 31, w = tid >> 5;   // warp w = batch w
    unsigned word = g_pos_bits[w * 32 + lane];
    int cnt = __popc(word);
    int incl = cnt;
    #pragma unroll
    for (int off = 1; off < 32; off <<= 1) {
        int t = __shfl_up_sync(0xffffffffu, incl, off);
        if (lane >= off) incl += t;
    }
    int excl = incl - cnt;
    int np = __shfl_sync(0xffffffffu, incl, 31);
    if (lane == 0) sm_npos[w] = np;
    __syncthreads();
    if (w == 0) {
        int v = (lane < B) ? sm_npos[lane] : 0;
        int inc2 = v;
        #pragma unroll
        for (int off = 1; off < 32; off <<= 1) {
            int t = __shfl_up_sync(0xffffffffu, inc2, off);
            if (lane >= off) inc2 += t;
        }
        if (lane < B) {
            sm_base[lane] = inc2 - v;
            g_batch_base[lane] = inc2 - v;
            g_npos[lane] = v;
        }
        if (lane == B - 1) g_mtot = inc2;
    }
    __syncthreads();
    int base = sm_base[w] + excl;
    int c0 = lane * 32, r = 0;
    while (word) {
        int bit = __ffs(word) - 1;
        word &= word - 1;
        g_row_b[base + r] = w;
        g_row_c[base + r] = c0 + bit;
        r++;
    }
}

// ---------------------------------------------------------------------------
// K4: gather + normalize packed anchor rows (grid-stride, 192 threads).
// ---------------------------------------------------------------------------
__global__ void k_gnorm(const float* __restrict__ f, int C, int D) {
    __shared__ float sm[8];
    int mtot = g_mtot, tid = threadIdx.x;
    for (int j = blockIdx.x; j < mtot; j += gridDim.x) {
        int b = g_row_b[j], c = g_row_c[j];
        const float4* row = (const float4*)(f + ((size_t)b * C + c) * D);
        float4 v = row[tid];
        float ss = v.x * v.x + v.y * v.y + v.z * v.z + v.w * v.w;
        float tot = bred_sum_f(ss, sm, 6);
        float inv = 1.f / fmaxf(sqrtf(tot), 1e-12f);
        float4 o = make_float4(v.x * inv, v.y * inv, v.z * inv, v.w * inv);
        ((float4*)(g_Fn + (size_t)j * D))[tid] = o;
    }
}

// ---------------------------------------------------------------------------
// K5: packed GEMM S[Mtot,1024] = Fn[Mtot,768] @ Pn^T. 64x64x16 tiles, 128 thr,
// 8x4 per-thread tile, register prefetch of the next k-slab.
// ---------------------------------------------------------------------------
__global__ void __launch_bounds__(128) k_gemm(int C, int D) {
    __shared__ __align__(16) float As[GBK][GBM + 4];
    __shared__ __align__(16) float Bs[GBK][GBN + 4];
    int mtot = g_mtot;
    int n0 = blockIdx.x * GBN;
    int tid = threadIdx.x, tx = tid & 15, ty = tid >> 4;
    int lm = tid >> 1, lk = (tid & 1) * 8;   // load mapping

    for (int mb = blockIdx.y; mb * GBM < mtot; mb += gridDim.y) {
        int m0 = mb * GBM;
        float acc[8][4];
        #pragma unroll
        for (int i = 0; i < 8; i++)
            #pragma unroll
            for (int q = 0; q < 4; q++) acc[i][q] = 0.f;

        const float* ap = g_Fn + (size_t)(m0 + lm) * D + lk;
        const float* bp = g_Pn + (size_t)(n0 + lm) * D + lk;

        float4 a0 = *(const float4*)ap,       a1 = *(const float4*)(ap + 4);
        float4 b0 = *(const float4*)bp,       b1 = *(const float4*)(bp + 4);

        for (int k0 = 0; k0 < D; k0 += GBK) {
            As[lk + 0][lm] = a0.x; As[lk + 1][lm] = a0.y; As[lk + 2][lm] = a0.z; As[lk + 3][lm] = a0.w;
            As[lk + 4][lm] = a1.x; As[lk + 5][lm] = a1.y; As[lk + 6][lm] = a1.z; As[lk + 7][lm] = a1.w;
            Bs[lk + 0][lm] = b0.x; Bs[lk + 1][lm] = b0.y; Bs[lk + 2][lm] = b0.z; Bs[lk + 3][lm] = b0.w;
            Bs[lk + 4][lm] = b1.x; Bs[lk + 5][lm] = b1.y; Bs[lk + 6][lm] = b1.z; Bs[lk + 7][lm] = b1.w;
            __syncthreads();
            if (k0 + GBK < D) {   // prefetch next slab
                a0 = *(const float4*)(ap + k0 + GBK); a1 = *(const float4*)(ap + k0 + GBK + 4);
                b0 = *(const float4*)(bp + k0 + GBK); b1 = *(const float4*)(bp + k0 + GBK + 4);
            }
            #pragma unroll
            for (int kk = 0; kk < GBK; kk++) {
                float4 A0 = *(const float4*)&As[kk][ty * 8];
                float4 A1 = *(const float4*)&As[kk][ty * 8 + 4];
                float4 B0 = *(const float4*)&Bs[kk][tx * 4];
                float am[8] = {A0.x, A0.y, A0.z, A0.w, A1.x, A1.y, A1.z, A1.w};
                float bn[4] = {B0.x, B0.y, B0.z, B0.w};
                #pragma unroll
                for (int i = 0; i < 8; i++)
                    #pragma unroll
                    for (int q = 0; q < 4; q++) acc[i][q] += am[i] * bn[q];
            }
            __syncthreads();
        }
        #pragma unroll
        for (int i = 0; i < 8; i++) {
            int row = m0 + ty * 8 + i;
            *(float4*)(g_S + (size_t)row * C + n0 + tx * 4) =
                make_float4(acc[i][0], acc[i][1], acc[i][2], acc[i][3]);
        }
    }
}

// ---------------------------------------------------------------------------
// K6: per-anchor loss via exact radix select of the Khard-th largest negative
// (ties contribute identical exp values => value-threshold is exact).
// 256 threads, 4 elements each, grid-stride over packed rows.
// ---------------------------------------------------------------------------
__global__ void __launch_bounds__(256) k_select(int C, int Khard, float tau_inv) {
    __shared__ int   hist[256];
    __shared__ int   scanbuf[256];
    __shared__ float s_pos;
    __shared__ int   s_digit, s_sexcl;
    __shared__ float smf[8];
    __shared__ int   smi[8];
    __shared__ unsigned smu[8];

    int mtot = g_mtot, tid = threadIdx.x;

    for (int j = blockIdx.x; j < mtot; j += gridDim.x) {
        int b = g_row_b[j];
        int posc = g_row_c[j];
        float4 v = ((const float4*)(g_S + (size_t)j * C))[tid];
        float vals[4] = {v.x, v.y, v.z, v.w};
        int e0 = tid * 4;
        unsigned pw = g_pos_bits[b * 32 + (tid >> 3)];
        unsigned rw = g_rand_bits[b * 32 + (tid >> 3)];
        unsigned sh = (tid & 7) * 4;
        unsigned pn = (pw >> sh) & 0xF;
        unsigned rn = (rw >> sh) & 0xF;

        unsigned keys[4];
        #pragma unroll
        for (int q = 0; q < 4; q++)
            keys[q] = ((pn >> q) & 1) ? 0u : f2key(vals[q]);

        if (posc >= e0 && posc < e0 + 4) s_pos = vals[posc - e0];

        unsigned mk = max(max(keys[0], keys[1]), max(keys[2], keys[3]));
        unsigned maxkey = bred_max_u(mk, smu, 8);

        // exact 4-pass radix select of the Khard-th largest key
        unsigned prefix = 0;
        int Krem = Khard;
        #pragma unroll
        for (int p = 0; p < 4; p++) {
            int shift = 24 - 8 * p;
            unsigned himask = (p == 0) ? 0u : (0xFFFFFFFFu << (shift + 8));
            hist[tid] = 0;
            __syncthreads();
            #pragma unroll
            for (int q = 0; q < 4; q++)
                if (keys[q] != 0u && (keys[q] & himask) == prefix)
                    atomicAdd(&hist[(keys[q] >> shift) & 0xFF], 1);
            __syncthreads();
            scanbuf[tid] = hist[255 - tid];
            __syncthreads();
            #pragma unroll
            for (int off = 1; off < 256; off <<= 1) {
                int t2 = (tid >= off) ? scanbuf[tid - off] : 0;
                __syncthreads();
                scanbuf[tid] += t2;
                __syncthreads();
            }
            int sincl = scanbuf[255 - tid];
            int sexcl = sincl - hist[tid];
            if (sexcl < Krem && Krem <= sincl) { s_digit = tid; s_sexcl = sexcl; }
            __syncthreads();
            prefix |= ((unsigned)s_digit) << shift;
            Krem -= s_sexcl;
            __syncthreads();
        }
        unsigned vkey = prefix;
        float vstar = key2f(vkey);
        float m = key2f(maxkey);

        float se = 0.f;
        int cg = 0;
        #pragma unroll
        for (int q = 0; q < 4; q++) {
            float ex = expf((vals[q] - m) * tau_inv);
            if (keys[q] > vkey) { se += ex; cg++; }
            if ((rn >> q) & 1) se += ex;
        }
        float se_tot = bred_sum_f(se, smf, 8);
        int cg_tot = bred_sum_i(cg, smi, 8);

        if (tid == 0) {
            float total = se_tot + (float)(Khard - cg_tot) * expf((vstar - m) * tau_inv);
            float lse = m * tau_inv + logf(total);
            float pos = s_pos * tau_inv;
            float mx = fmaxf(pos, lse), mn = fminf(pos, lse);
            g_loss[j] = (mx + log1pf(expf(mn - mx))) - pos;
        }
        __syncthreads();
    }
}

// ---------------------------------------------------------------------------
// K7: final reduction over packed losses.
// ---------------------------------------------------------------------------
__global__ void k_final(float* __restrict__ out, int B) {
    __shared__ float sm[8];
    int tid = threadIdx.x;
    float result = 0.f;
    for (int b = 0; b < B; b++) {
        int base = g_batch_base[b], np = g_npos[b];
        float part = 0.f;
        for (int x = tid; x < np; x += blockDim.x) part += g_loss[base + x];
        float s = bred_sum_f(part, sm, 8);
        if (tid == 0) result += s / (float)(np < 1 ? 1 : np);
    }
    if (tid == 0) out[0] = result / (float)B;
}

// ---------------------------------------------------------------------------
extern "C" void kernel_launch(void* const* d_in, const int* in_sizes, int n_in,
                              void* d_out, int out_size) {
    const float* f  = (const float*)d_in[0];
    const float* p  = (const float*)d_in[1];
    const int*   tw = (const int*)d_in[2];
    const float* rs = (const float*)d_in[3];

    int nf = in_sizes[0], npx = in_sizes[1], nt = in_sizes[2];
    int B = nf / npx;          // 16
    int C = nt / B;            // 1024
    int D = npx / C;           // 768
    int K = C - 1;
    int Khard = (int)((double)K * 0.3);   // 306
    int Krand = K - Khard;                // 717
    float tau_inv = 1.0f / 0.1f;

    k_mask   <<<1, 1024>>>(tw, nt);
    k_norm_p <<<C, D / 4>>>(p, D);
    k_rand   <<<B, C>>>(rs, C, Krand);
    k_compact<<<1, B * 32>>>(B);
    k_gnorm  <<<256, D / 4>>>(f, C, D);
    k_gemm   <<<dim3(C / GBN, 16), 128>>>(C, D);
    k_select <<<1024, 256>>>(C, Khard, tau_inv);
    k_final  <<<1, 256>>>((float*)d_out, B);
}